// round 4
// baseline (speedup 1.0000x reference)
#include <cuda_runtime.h>

// UnionLayer: out[b, 0:256]   = -1/(-1 + sum_d log(1 - (1-x[b,d]) * W_con[n,d]))
//             out[b, 256:512] = 1 - ( -1/(-1 + sum_d log(1 - x[b,d] * W_dis[n,d])) )
// B=1024, D=512, N=256.
// R4: fp32 mainloop (R1 math, known-good), but:
//   - 512-thread CTA, in-CTA split-K: group g in {0,1} handles D-half [256g, 256g+256)
//     -> 16 warps/SM (4 per SMSP) instead of 8, hides LDS/FFMA latency
//   - k-major smem, float4 LDS: 2 LDS.128 per k instead of 8 scalar LDS
//   - negation folded into A fill (term = fma(a,b,1), a = -u)
//   - log2 accumulation, single ln2 fold in epilogue
// Tile: CTA 64x64, thread tile 4x4, BK=16 double-buffered per group.

#define BM 64
#define BN 64
#define BK 16
#define SA 68          // k-major row stride (floats): 16B-aligned float4 reads
#define SB 68
#define KHALF 256      // D per group
#define NCHUNK (KHALF / BK)   // 16
#define DDIM 512
#define NOUT 512
#define NCOLS 256

__global__ __launch_bounds__(512) void union_kernel(
    const float* __restrict__ x,
    const float* __restrict__ Wcon,
    const float* __restrict__ Wdis,
    float* __restrict__ out)
{
    __shared__ float As[2][2][BK * SA];   // [group][buf][k*SA + m], holds -u
    __shared__ float Bs[2][2][BK * SB];   // [group][buf][k*SB + n], holds w

    const int tid512 = threadIdx.x;
    const int group  = tid512 >> 8;       // 0 or 1: which D-half
    const int tid    = tid512 & 255;
    const int tx = tid & 15;              // n = 4*tx .. 4*tx+3
    const int ty = tid >> 4;              // m = 4*ty .. 4*ty+3
    const int bn0 = blockIdx.x * BN;
    const int bm0 = blockIdx.y * BM;
    const int z   = blockIdx.z;           // 0 = con, 1 = dis
    const float* __restrict__ W = z ? Wdis : Wcon;
    const int gk0 = group * KHALF;

    // fill indices: 256 threads cover 64 rows x 16 k (one float4 of k each)
    const int fr = tid >> 2;              // row 0..63
    const int fc = (tid & 3) << 2;        // k offset 0,4,8,12

    float prod[16], acc[16];
#pragma unroll
    for (int i = 0; i < 16; i++) { prod[i] = 1.0f; acc[i] = 0.0f; }

    float4 xv, wv;

    // ---- fill chunk 0 ----
    xv = *reinterpret_cast<const float4*>(&x[(bm0 + fr) * DDIM + gk0 + fc]);
    wv = *reinterpret_cast<const float4*>(&W[(bn0 + fr) * DDIM + gk0 + fc]);
    {
        float a0, a1, a2, a3;
        if (z == 0) { a0 = xv.x - 1.0f; a1 = xv.y - 1.0f; a2 = xv.z - 1.0f; a3 = xv.w - 1.0f; }
        else        { a0 = -xv.x;       a1 = -xv.y;       a2 = -xv.z;       a3 = -xv.w;       }
        As[group][0][(fc + 0) * SA + fr] = a0;
        As[group][0][(fc + 1) * SA + fr] = a1;
        As[group][0][(fc + 2) * SA + fr] = a2;
        As[group][0][(fc + 3) * SA + fr] = a3;
        Bs[group][0][(fc + 0) * SB + fr] = wv.x;
        Bs[group][0][(fc + 1) * SB + fr] = wv.y;
        Bs[group][0][(fc + 2) * SB + fr] = wv.z;
        Bs[group][0][(fc + 3) * SB + fr] = wv.w;
    }
    __syncthreads();

    for (int ck = 0; ck < NCHUNK; ck++) {
        const int buf = ck & 1;

        // prefetch next chunk global -> regs
        if (ck + 1 < NCHUNK) {
            int d0 = gk0 + (ck + 1) * BK;
            xv = *reinterpret_cast<const float4*>(&x[(bm0 + fr) * DDIM + d0 + fc]);
            wv = *reinterpret_cast<const float4*>(&W[(bn0 + fr) * DDIM + d0 + fc]);
        }

        // ---- compute on buf ----
        const float* __restrict__ Ap = As[group][buf];
        const float* __restrict__ Bp = Bs[group][buf];
#pragma unroll
        for (int k = 0; k < BK; k++) {
            float4 a = *reinterpret_cast<const float4*>(&Ap[k * SA + 4 * ty]);
            float4 b = *reinterpret_cast<const float4*>(&Bp[k * SB + 4 * tx]);
            prod[ 0] *= fmaf(a.x, b.x, 1.0f);
            prod[ 1] *= fmaf(a.x, b.y, 1.0f);
            prod[ 2] *= fmaf(a.x, b.z, 1.0f);
            prod[ 3] *= fmaf(a.x, b.w, 1.0f);
            prod[ 4] *= fmaf(a.y, b.x, 1.0f);
            prod[ 5] *= fmaf(a.y, b.y, 1.0f);
            prod[ 6] *= fmaf(a.y, b.z, 1.0f);
            prod[ 7] *= fmaf(a.y, b.w, 1.0f);
            prod[ 8] *= fmaf(a.z, b.x, 1.0f);
            prod[ 9] *= fmaf(a.z, b.y, 1.0f);
            prod[10] *= fmaf(a.z, b.z, 1.0f);
            prod[11] *= fmaf(a.z, b.w, 1.0f);
            prod[12] *= fmaf(a.w, b.x, 1.0f);
            prod[13] *= fmaf(a.w, b.y, 1.0f);
            prod[14] *= fmaf(a.w, b.z, 1.0f);
            prod[15] *= fmaf(a.w, b.w, 1.0f);
        }

        // store prefetched chunk to other buffer
        if (ck + 1 < NCHUNK) {
            const int nb = buf ^ 1;
            float a0, a1, a2, a3;
            if (z == 0) { a0 = xv.x - 1.0f; a1 = xv.y - 1.0f; a2 = xv.z - 1.0f; a3 = xv.w - 1.0f; }
            else        { a0 = -xv.x;       a1 = -xv.y;       a2 = -xv.z;       a3 = -xv.w;       }
            As[group][nb][(fc + 0) * SA + fr] = a0;
            As[group][nb][(fc + 1) * SA + fr] = a1;
            As[group][nb][(fc + 2) * SA + fr] = a2;
            As[group][nb][(fc + 3) * SA + fr] = a3;
            Bs[group][nb][(fc + 0) * SB + fr] = wv.x;
            Bs[group][nb][(fc + 1) * SB + fr] = wv.y;
            Bs[group][nb][(fc + 2) * SB + fr] = wv.z;
            Bs[group][nb][(fc + 3) * SB + fr] = wv.w;
        }

        // flush every 4 chunks (64 terms; each in (0.5,1] -> prod >= 0.5^64, fp32-safe)
        if ((ck & 3) == 3) {
#pragma unroll
            for (int i = 0; i < 16; i++) {
                acc[i] += __log2f(prod[i]);
                prod[i] = 1.0f;
            }
        }

        __syncthreads();
    }

    // ---- cross-group reduction (reuse As region as scratch) ----
    float* red = &As[0][0][0];            // need 256*16 floats = 16KB <= As size
    if (group == 1) {
#pragma unroll
        for (int j = 0; j < 4; j++) {
            float4 v = make_float4(acc[4 * j + 0], acc[4 * j + 1],
                                   acc[4 * j + 2], acc[4 * j + 3]);
            *reinterpret_cast<float4*>(&red[tid * 16 + 4 * j]) = v;
        }
    }
    __syncthreads();

    if (group == 0) {
        const float LN2 = 0.69314718055994530942f;
#pragma unroll
        for (int mm = 0; mm < 4; mm++) {
            int row = bm0 + ty * 4 + mm;
            float v[4];
#pragma unroll
            for (int nn = 0; nn < 4; nn++) {
                int i = mm * 4 + nn;
                float s = acc[i] + red[tid * 16 + i];   // total log2-sum
                float denom = fmaf(-LN2, s, 1.0f);      // 1 - ln(prod)
                float y = 1.0f / denom;
                v[nn] = z ? (1.0f - y) : y;
            }
            float4 o = make_float4(v[0], v[1], v[2], v[3]);
            *reinterpret_cast<float4*>(&out[row * NOUT + z * NCOLS + bn0 + tx * 4]) = o;
        }
    }
}

extern "C" void kernel_launch(void* const* d_in, const int* in_sizes, int n_in,
                              void* d_out, int out_size)
{
    const float* x    = (const float*)d_in[0];
    const float* Wcon = (const float*)d_in[1];
    const float* Wdis = (const float*)d_in[2];
    float* out = (float*)d_out;

    dim3 grid(NCOLS / BN, 1024 / BM, 2);   // (4, 16, 2) = 128 CTAs, 1 per SM
    union_kernel<<<grid, 512>>>(x, Wcon, Wdis, out);
}

// round 6
// speedup vs baseline: 1.5151x; 1.5151x over previous
#include <cuda_runtime.h>
#include <cuda_fp16.h>
#include <cstdint>

// UnionLayer via Taylor expansion -> fp16 tensor-core GEMM (mma.sync, generic PTX).
//   -log(1-t) = sum_{n=1..8} t^n / n,  t = u*w in [0, 0.5)   (tail < 2e-4 worst)
//   S[b,nh]   = sum_d sum_n u^n * (w^n / n)  == GEMM, K = 8*512
//   con: u = 1-x, y = 1/(1+S);  dis: u = x, y = 1 - 1/(1+S)
// All operands generated IN REGISTERS in mma fragment layout (no smem at all):
//   A frag (m16k16): rows g, g+8; k = 2*t4 + {0,1,8,9}   (g = lane>>2, t4 = lane&3)
//   B frag (k16n8):  n = g;      k = same
// Each thread owns 4 m-rows / 4 n-rows x 4 d-pairs; power chains advance in place.
// CTA: 128 threads = 4 warps, each warp a 32Mx32N tile -> CTA 128x32.
// Grid (8, 8, 2) = 128 CTAs. K processed as 16 chunks of 32 d (8 terms inside).

#define DDIM    512
#define NOUT    512
#define NCOLS   256
#define NTERMS  8
#define DCHUNK  32
#define NCHUNKS 16
#define MTILE   128
#define NTILE   32

__device__ __forceinline__ void mma16816(float* c, uint32_t a0, uint32_t a1,
                                         uint32_t a2, uint32_t a3,
                                         uint32_t b0, uint32_t b1) {
    asm volatile(
        "mma.sync.aligned.m16n8k16.row.col.f32.f16.f16.f32 "
        "{%0,%1,%2,%3}, {%4,%5,%6,%7}, {%8,%9}, {%0,%1,%2,%3};"
        : "+f"(c[0]), "+f"(c[1]), "+f"(c[2]), "+f"(c[3])
        : "r"(a0), "r"(a1), "r"(a2), "r"(a3), "r"(b0), "r"(b1));
}

__device__ __forceinline__ uint32_t h2u(__half2 h) {
    return *reinterpret_cast<uint32_t*>(&h);
}

__global__ __launch_bounds__(128) void union_mma_kernel(
    const float* __restrict__ x,
    const float* __restrict__ Wcon,
    const float* __restrict__ Wdis,
    float* __restrict__ out)
{
    const int tid  = threadIdx.x;
    const int wid  = tid >> 5;          // warp 0..3 -> m offset wid*32
    const int lane = tid & 31;
    const int g    = lane >> 2;         // 0..7
    const int t4   = lane & 3;          // 0..3
    const int bn0  = blockIdx.x * NTILE;
    const int bm0  = blockIdx.y * MTILE;
    const int z    = blockIdx.z;        // 0 = con, 1 = dis
    const float* __restrict__ W = z ? Wdis : Wcon;

    // Single base pointer each; rows r*8 apart resolve to LDG immediate offsets.
    const float* __restrict__ pA = &x[(bm0 + wid * 32 + g) * DDIM + 2 * t4];
    const float* __restrict__ pB = &W[(bn0 + g) * DDIM + 2 * t4];

    float acc[2][4][4];                 // [mt][nt][c]
#pragma unroll
    for (int mt = 0; mt < 2; mt++)
#pragma unroll
        for (int nt = 0; nt < 4; nt++)
#pragma unroll
            for (int c = 0; c < 4; c++) acc[mt][nt][c] = 0.0f;

    // staged raw loads: [row 0..3][dpair 0..3], dpair p -> d offset p*8 (+{0,1})
    float2 fA[4][4], fB[4][4];
#pragma unroll
    for (int r = 0; r < 4; r++)
#pragma unroll
        for (int p = 0; p < 4; p++) {
            fA[r][p] = *reinterpret_cast<const float2*>(pA + r * 8 * DDIM + p * 8);
            fB[r][p] = *reinterpret_cast<const float2*>(pB + r * 8 * DDIM + p * 8);
        }

    __half2 baseA[4][4], baseB[4][4], curA[4][4], curB[4][4];

    // chain coefficients: curB_n = curB_{n-1} * w * (n/(n+1))  => w^{n+1}/(n+1)
    const float kf[NTERMS] = {0.f, 0.5f, 2.f/3.f, 0.75f, 0.8f, 5.f/6.f, 6.f/7.f, 0.875f};

#pragma unroll 1
    for (int ck = 0; ck < NCHUNKS; ck++) {
        // ---- convert staged floats -> half2 bases (A transformed to u) ----
#pragma unroll
        for (int r = 0; r < 4; r++)
#pragma unroll
            for (int p = 0; p < 4; p++) {
                float ux = fA[r][p].x, uy = fA[r][p].y;
                if (z == 0) { ux = 1.0f - ux; uy = 1.0f - uy; }
                baseA[r][p] = __floats2half2_rn(ux, uy);
                baseB[r][p] = __floats2half2_rn(fB[r][p].x, fB[r][p].y);
                curA[r][p]  = baseA[r][p];
                curB[r][p]  = baseB[r][p];
            }

        // ---- prefetch next chunk raw (latency hidden by term loop) ----
        if (ck + 1 < NCHUNKS) {
            const float* qA = pA + (ck + 1) * DCHUNK;
            const float* qB = pB + (ck + 1) * DCHUNK;
#pragma unroll
            for (int r = 0; r < 4; r++)
#pragma unroll
                for (int p = 0; p < 4; p++) {
                    fA[r][p] = *reinterpret_cast<const float2*>(qA + r * 8 * DDIM + p * 8);
                    fB[r][p] = *reinterpret_cast<const float2*>(qB + r * 8 * DDIM + p * 8);
                }
        }

        // ---- 8 Taylor terms ----
#pragma unroll
        for (int n = 0; n < NTERMS; n++) {
            if (n) {
                const __half2 kfh = __float2half2_rn(kf[n]);
#pragma unroll
                for (int r = 0; r < 4; r++)
#pragma unroll
                    for (int p = 0; p < 4; p++) {
                        curA[r][p] = __hmul2(curA[r][p], baseA[r][p]);
                        curB[r][p] = __hmul2(__hmul2(curB[r][p], baseB[r][p]), kfh);
                    }
            }
            // two k16 blocks per term: db=0 uses dpairs {0,1}, db=1 uses {2,3}
#pragma unroll
            for (int db = 0; db < 2; db++) {
                const int p0 = db * 2, p1 = db * 2 + 1;
#pragma unroll
                for (int mt = 0; mt < 2; mt++) {
                    uint32_t a0 = h2u(curA[mt * 2 + 0][p0]);
                    uint32_t a1 = h2u(curA[mt * 2 + 1][p0]);
                    uint32_t a2 = h2u(curA[mt * 2 + 0][p1]);
                    uint32_t a3 = h2u(curA[mt * 2 + 1][p1]);
#pragma unroll
                    for (int nt = 0; nt < 4; nt++) {
                        mma16816(acc[mt][nt], a0, a1, a2, a3,
                                 h2u(curB[nt][p0]), h2u(curB[nt][p1]));
                    }
                }
            }
        }
    }

    // ---- epilogue: y = 1/(1+S); dis: 1-y ----
#pragma unroll
    for (int mt = 0; mt < 2; mt++) {
#pragma unroll
        for (int half = 0; half < 2; half++) {      // c0c1 (row+0) / c2c3 (row+8)
            int m = bm0 + wid * 32 + mt * 16 + g + half * 8;
#pragma unroll
            for (int nt = 0; nt < 4; nt++) {
                float S0 = acc[mt][nt][half * 2 + 0];
                float S1 = acc[mt][nt][half * 2 + 1];
                float y0 = 1.0f / (1.0f + S0);
                float y1 = 1.0f / (1.0f + S1);
                if (z) { y0 = 1.0f - y0; y1 = 1.0f - y1; }
                int col = bn0 + nt * 8 + 2 * t4;
                *reinterpret_cast<float2*>(&out[m * NOUT + z * NCOLS + col]) =
                    make_float2(y0, y1);
            }
        }
    }
}

extern "C" void kernel_launch(void* const* d_in, const int* in_sizes, int n_in,
                              void* d_out, int out_size)
{
    const float* x    = (const float*)d_in[0];
    const float* Wcon = (const float*)d_in[1];
    const float* Wdis = (const float*)d_in[2];
    float* out = (float*)d_out;

    dim3 grid(NCOLS / NTILE, 1024 / MTILE, 2);   // (8, 8, 2) = 128 CTAs
    union_mma_kernel<<<grid, 128>>>(x, Wcon, Wdis, out);
}